// round 7
// baseline (speedup 1.0000x reference)
#include <cuda_runtime.h>
#include <cuda_bf16.h>
#include <cstdint>

#define EPS_F 0.01f

constexpr int B = 16;
constexpr int H = 1024;
constexpr int W = 1024;

// Persistent column walker: CTA = 256 threads (32x8), tile 128x16, NT=4 tiles.
constexpr int TX = 32;
constexpr int TY = 8;
constexpr int THREADS = TX * TY;
constexpr int TILE_W = 128;
constexpr int TILE_H = 16;
constexpr int NT = 4;                     // tiles per CTA (64 rows)

// Stage: raw c0,c1 tiles with halo. rows y0-1..y0+16 (18), cols tx0-4..tx0+131 (136)
constexpr int SH_H = TILE_H + 2;          // 18
constexpr int SH_W = 136;
constexpr int F4_PER_ROW = SH_W / 4;      // 34
constexpr int TASKS_CH = SH_H * F4_PER_ROW;   // 612
constexpr int TASKS = 2 * TASKS_CH;           // 1224 (both channels)

__device__ __forceinline__ float fmax3(float a, float b, float c) {
    return fmaxf(fmaxf(a, b), c);
}

__device__ __forceinline__ void cp16(uint32_t dst_smem, const float* src, bool pred) {
    const int sz = pred ? 16 : 0;   // src_size=0 => zero-fill 16B
    asm volatile("cp.async.cg.shared.global [%0], [%1], 16, %2;\n"
                 :: "r"(dst_smem), "l"(src), "r"(sz) : "memory");
}

// sbuf[stage][channel][row][col]
__shared__ float sbuf_dummy_decl_guard; // (unused; real buffer inside kernel)

__global__ __launch_bounds__(THREADS) void detection_head_kernel(
    const float* __restrict__ seg,   // [B, 2, H, W]
    float* __restrict__ out)         // [B*H*W] xnms | [B*2*H*W] seg copy
{
    __shared__ float sb[2][2][SH_H][SH_W];   // 39,168 B

    const int b   = blockIdx.z;
    const int col0y = blockIdx.y * (TILE_H * NT);   // top row of this CTA's column
    const int tx0 = blockIdx.x * TILE_W;

    const float* __restrict__ c0 = seg + (size_t)b * 2 * H * W;
    const float* __restrict__ c1 = c0 + (size_t)H * W;
    float* __restrict__ oseg = out + (size_t)B * H * W + (size_t)b * 2 * H * W;
    float* __restrict__ oxn  = out + (size_t)b * H * W;

    const int tid  = threadIdx.y * TX + threadIdx.x;
    const int lane = threadIdx.x;
    const int lc   = threadIdx.x * 4;     // local col 0..124
    const int yr0  = threadIdx.y * 2;     // local row pair base (0..14)

    // ---- async stage fill: raw c0,c1 (OOB -> zero-fill) ----
    auto issue_stage = [&](int st, int y0) {
        #pragma unroll
        for (int it = 0; it < 5; it++) {
            const int idx = tid + it * THREADS;
            if (idx >= TASKS) break;
            const int ch  = idx >= TASKS_CH;
            const int rem = idx - ch * TASKS_CH;
            const unsigned r = (unsigned)rem / F4_PER_ROW;       // 0..17
            const unsigned c = (unsigned)rem - r * F4_PER_ROW;   // 0..33
            const int gy = y0 - 1 + (int)r;
            const int gx = tx0 - 4 + (int)(c * 4);
            const bool ok = ((unsigned)gy < (unsigned)H) && ((unsigned)gx < (unsigned)W);
            const int gyc = min(max(gy, 0), H - 1);
            const int gxc = min(max(gx, 0), W - 4);
            const float* src = (ch ? c1 : c0) + (size_t)gyc * W + gxc;
            const uint32_t dst = (uint32_t)__cvta_generic_to_shared(&sb[st][ch][r][c * 4]);
            cp16(dst, src, ok);
        }
        asm volatile("cp.async.commit_group;\n" ::: "memory");
    };

    issue_stage(0, col0y);

    for (int t = 0; t < NT; t++) {
        const int y0 = col0y + t * TILE_H;
        const int st = t & 1;

        if (t + 1 < NT) {
            issue_stage((t + 1) & 1, y0 + TILE_H);
            asm volatile("cp.async.wait_group 1;\n" ::: "memory");
        } else {
            asm volatile("cp.async.wait_group 0;\n" ::: "memory");
        }
        __syncthreads();

        // ---- compute 4x2 outputs from stage st ----
        // Local smem rows yr0..yr0+3 = global rows y0-1+yr0 .. y0+2+yr0.
        const unsigned FULL = 0xFFFFFFFFu;
        float w[4][6];
        float4 cc0[4], cc1[4];
        #pragma unroll
        for (int r = 0; r < 4; r++) {
            cc0[r] = *(const float4*)&sb[st][0][yr0 + r][lc + 4];
            cc1[r] = *(const float4*)&sb[st][1][yr0 + r][lc + 4];
            w[r][1] = cc1[r].x - cc0[r].x - EPS_F;
            w[r][2] = cc1[r].y - cc0[r].y - EPS_F;
            w[r][3] = cc1[r].z - cc0[r].z - EPS_F;
            w[r][4] = cc1[r].w - cc0[r].w - EPS_F;
            float lft = __shfl_up_sync(FULL, w[r][4], 1);
            float rgt = __shfl_down_sync(FULL, w[r][1], 1);
            if (lane == 0)
                lft = sb[st][1][yr0 + r][3] - sb[st][0][yr0 + r][3] - EPS_F;
            if (lane == 31)
                rgt = sb[st][1][yr0 + r][132] - sb[st][0][yr0 + r][132] - EPS_F;
            w[r][0] = lft;
            w[r][5] = rgt;
        }

        float h3[4][4];
        #pragma unroll
        for (int r = 0; r < 4; r++)
            #pragma unroll
            for (int i = 0; i < 4; i++)
                h3[r][i] = fmax3(w[r][i], w[r][i + 1], w[r][i + 2]);

        const int gy0 = y0 + yr0;           // first owned output row
        const int gx  = tx0 + lc;
        const size_t g0 = (size_t)gy0 * W + gx;

        float4 o0, o1;
        float* o0p = &o0.x;
        float* o1p = &o1.x;
        #pragma unroll
        for (int i = 0; i < 4; i++) {
            float m0 = fmax3(h3[0][i], fmaxf(w[1][i], w[1][i + 2]), h3[2][i]);
            m0 = fmaxf(m0, 0.0f);
            const float x0 = w[1][i + 1];
            o0p[i] = (x0 > m0) ? x0 : 0.0f;
            float m1 = fmax3(h3[1][i], fmaxf(w[2][i], w[2][i + 2]), h3[3][i]);
            m1 = fmaxf(m1, 0.0f);
            const float x1 = w[2][i + 1];
            o1p[i] = (x1 > m1) ? x1 : 0.0f;
        }
        __stcs((float4*)(oxn + g0), o0);
        __stcs((float4*)(oxn + g0 + W), o1);

        // seg copy for the two owned rows (data already in registers)
        __stcs((float4*)(oseg + g0), cc0[1]);
        __stcs((float4*)(oseg + g0 + W), cc0[2]);
        __stcs((float4*)(oseg + (size_t)H * W + g0), cc1[1]);
        __stcs((float4*)(oseg + (size_t)H * W + g0 + W), cc1[2]);

        __syncthreads();   // stage st reusable only after all threads done
    }
}

extern "C" void kernel_launch(void* const* d_in, const int* in_sizes, int n_in,
                              void* d_out, int out_size)
{
    const float* seg = (const float*)d_in[0];
    float* out = (float*)d_out;

    dim3 block(TX, TY, 1);
    dim3 grid(W / TILE_W, H / (TILE_H * NT), B);  // 8 x 16 x 16 = 2048 CTAs
    detection_head_kernel<<<grid, block>>>(seg, out);
}

// round 9
// speedup vs baseline: 1.0786x; 1.0786x over previous
#include <cuda_runtime.h>
#include <cuda_bf16.h>
#include <cstdint>

#define EPS_F 0.01f

constexpr int B = 16;
constexpr int H = 1024;
constexpr int W = 1024;

// Tile: 128 cols x 32 rows per CTA. Block 32x8 = 256 threads.
// Each thread computes a 4-wide x 4-high output block. Warp = one thread-row.
constexpr int TX = 32;
constexpr int TY = 8;
constexpr int TILE_W = 128;
constexpr int TILE_H = 32;

// smem: rows ty0-1..ty0+32 (34), cols tx0-4..tx0+131 (136 = 34 float4)
constexpr int SH_H = TILE_H + 2;            // 34
constexpr int SH_W = 136;
constexpr int F4_PER_ROW = SH_W / 4;        // 34
constexpr int FILL_TASKS = SH_H * F4_PER_ROW;  // 1156

__device__ __forceinline__ float fmax3(float a, float b, float c) {
    return fmaxf(fmaxf(a, b), c);
}

// L2 evict_last access policy (created once per thread, reused for all loads).
__device__ __forceinline__ uint64_t mk_policy_el() {
    uint64_t pol;
    asm("createpolicy.fractional.L2::evict_last.b64 %0, 1.0;" : "=l"(pol));
    return pol;
}

// Vector load with L2 evict_last cache hint: pin the input in L2 so the
// streaming output stores (evict_first) cannot displace it between replays.
__device__ __forceinline__ float4 ldg_el(const float* p, uint64_t pol) {
    float4 v;
    asm("ld.global.nc.L2::cache_hint.v4.f32 {%0,%1,%2,%3}, [%4], %5;"
        : "=f"(v.x), "=f"(v.y), "=f"(v.z), "=f"(v.w) : "l"(p), "l"(pol));
    return v;
}

// Read one smem row's 6-wide window for this lane: center LDS.128 + shfl halo.
__device__ __forceinline__ void read_sr(
    const float (*sx)[SH_W], int sr, int lc, int lane, float w[6])
{
    const unsigned FULL = 0xFFFFFFFFu;
    const float4 ce = *(const float4*)&sx[sr][lc + 4];
    float lft = __shfl_up_sync(FULL, ce.w, 1);
    float rgt = __shfl_down_sync(FULL, ce.x, 1);
    if (lane == 0)  lft = sx[sr][3];
    if (lane == 31) rgt = sx[sr][132];
    w[0] = lft;
    w[1] = ce.x; w[2] = ce.y; w[3] = ce.z; w[4] = ce.w;
    w[5] = rgt;
}

__global__ __launch_bounds__(TX * TY) void detection_head_kernel(
    const float* __restrict__ seg,   // [B, 2, H, W]
    float* __restrict__ out)         // [B*H*W] xnms | [B*2*H*W] seg copy
{
    __shared__ float sx[SH_H][SH_W];

    const int b   = blockIdx.z;
    const int ty0 = blockIdx.y * TILE_H;
    const int tx0 = blockIdx.x * TILE_W;

    const float* __restrict__ c0 = seg + (size_t)b * 2 * H * W;
    const float* __restrict__ c1 = c0 + (size_t)H * W;
    float* __restrict__ oseg = out + (size_t)B * H * W + (size_t)b * 2 * H * W;

    const int tid  = threadIdx.y * TX + threadIdx.x;
    const int lane = threadIdx.x;
    const uint64_t pol = mk_policy_el();

    // ---- Fill smem with x = c1 - c0 - EPS (halo -> 0, exact: pool is
    // relu'd + zero-floored) AND stream the seg copy for interior pixels. ----
    #pragma unroll
    for (int idx = tid; idx < FILL_TASKS; idx += TX * TY) {
        const unsigned row = (unsigned)idx / F4_PER_ROW;       // 0..33
        const unsigned col = (unsigned)idx - row * F4_PER_ROW; // 0..33
        const int gy = ty0 - 1 + (int)row;
        const int gx = tx0 - 4 + (int)(col * 4);               // 16B aligned
        float4 v = make_float4(0.f, 0.f, 0.f, 0.f);
        if ((unsigned)gy < (unsigned)H && (unsigned)gx < (unsigned)W) {
            const size_t g = (size_t)gy * W + gx;
            const float4 a  = ldg_el(c0 + g, pol);
            const float4 bb = ldg_el(c1 + g, pol);
            v.x = bb.x - a.x - EPS_F;
            v.y = bb.y - a.y - EPS_F;
            v.z = bb.z - a.z - EPS_F;
            v.w = bb.w - a.w - EPS_F;
            // Interior of this CTA's tile: written exactly once chip-wide.
            if (row >= 1u && row <= (unsigned)TILE_H &&
                col >= 1u && col <= (unsigned)(TILE_W / 4)) {
                __stcs((float4*)(oseg + g), a);
                __stcs((float4*)(oseg + (size_t)H * W + g), bb);
            }
        }
        *(float4*)&sx[row][col * 4] = v;
    }
    __syncthreads();

    // ---- Compute: 4 output rows per thread, rolling 3-row window ----
    const int yr0 = threadIdx.y * 4;      // local row 0..28 (smem rows yr0..yr0+5)
    const int lc  = threadIdx.x * 4;      // local col 0..124

    float w_top[6], w_mid[6];
    read_sr(sx, yr0 + 0, lc, lane, w_top);
    read_sr(sx, yr0 + 1, lc, lane, w_mid);

    float h3t[4], h3m[4];
    #pragma unroll
    for (int i = 0; i < 4; i++) {
        h3t[i] = fmax3(w_top[i], w_top[i + 1], w_top[i + 2]);
        h3m[i] = fmax3(w_mid[i], w_mid[i + 1], w_mid[i + 2]);
    }

    const int gy0 = ty0 + yr0;
    const int gx  = tx0 + lc;
    float* __restrict__ oxn = out + (size_t)b * H * W;

    #pragma unroll
    for (int k = 0; k < 4; k++) {
        float w_bot[6], h3b[4];
        read_sr(sx, yr0 + k + 2, lc, lane, w_bot);
        #pragma unroll
        for (int i = 0; i < 4; i++)
            h3b[i] = fmax3(w_bot[i], w_bot[i + 1], w_bot[i + 2]);

        float4 o;
        float* op = &o.x;
        #pragma unroll
        for (int i = 0; i < 4; i++) {
            float m = fmax3(h3t[i], fmaxf(w_mid[i], w_mid[i + 2]), h3b[i]);
            m = fmaxf(m, 0.0f);
            const float x = w_mid[i + 1];
            op[i] = (x > m) ? x : 0.0f;
        }
        __stcs((float4*)(oxn + (size_t)(gy0 + k) * W + gx), o);

        #pragma unroll
        for (int i = 0; i < 4; i++) { h3t[i] = h3m[i]; h3m[i] = h3b[i]; }
        #pragma unroll
        for (int j = 0; j < 6; j++) w_mid[j] = w_bot[j];
    }
}

extern "C" void kernel_launch(void* const* d_in, const int* in_sizes, int n_in,
                              void* d_out, int out_size)
{
    const float* seg = (const float*)d_in[0];
    float* out = (float*)d_out;

    dim3 block(TX, TY, 1);
    dim3 grid(W / TILE_W, H / TILE_H, B);  // 8 x 32 x 16 = 4096 CTAs
    detection_head_kernel<<<grid, block>>>(seg, out);
}